// round 11
// baseline (speedup 1.0000x reference)
#include <cuda_runtime.h>
#include <cstddef>
#include <cstdint>

#define NPTS 1024
#define BATCH 32
#define MTOT 32768
#define EPS_BN 1e-5f

// ---------------- static scratch (no allocations allowed) ----------------
__device__ float g_z1[(size_t)MTOT * 64];
__device__ float g_z2[(size_t)MTOT * 64];
__device__ float g_z3[(size_t)MTOT * 64];
__device__ float g_z4[(size_t)MTOT * 128];
// z5 is never materialized: max-pool + stats are fused into the L5 GEMM epilogue
__device__ float g_z6[(size_t)MTOT * 512];
__device__ float g_z7[(size_t)MTOT * 256];
__device__ float g_z8[(size_t)MTOT * 128];
__device__ float g_z9[(size_t)MTOT * 128];

// per-channel stats, packed by layer offset:
// L1:0(64) L2:64 L3:128 L4:192(128) L5:320(1024) L6:1344(512) L7:1856(256) L8:2112(128) L9:2240(128) -> 2368
__device__ float g_sum[2368];
__device__ float g_sq[2368];
__device__ float g_mean[2368];
__device__ float g_rstd[2368];

__device__ unsigned g_max5[BATCH * 1024];   // order-monotone uint-mapped float max
__device__ float g_const6[BATCH * 512];     // per-batch gf contribution to layer 6

// ---------------- helpers ----------------
__device__ __forceinline__ float fast_tanh(float x) {
    // tanh(x) = 1 - 2/(exp(2x)+1); ex2.approx + rcp.approx, rel err ~1e-6
    float e, r;
    asm("ex2.approx.f32 %0, %1;" : "=f"(e) : "f"(x * 2.8853900817779268f)); // 2*log2(e)
    asm("rcp.approx.f32 %0, %1;" : "=f"(r) : "f"(e + 1.0f));
    return 1.0f - 2.0f * r;
}

// Jacobi polys, degree 3, a=b=1 (exact constants from the reference recurrence)
__device__ __forceinline__ void jacobi4(float t, float& p0, float& p1, float& p2, float& p3) {
    p0 = 1.0f;
    p1 = 2.0f * t;
    p2 = 1.875f * t * p1 - 0.75f;
    p3 = 1.8666666666666667f * t * p2 - 0.8f * p1;
}

__device__ __forceinline__ unsigned fmap(float f) {
    unsigned u = __float_as_uint(f);
    return (u & 0x80000000u) ? ~u : (u | 0x80000000u);
}
__device__ __forceinline__ float funmap(unsigned u) {
    return (u & 0x80000000u) ? __uint_as_float(u & 0x7fffffffu) : __uint_as_float(~u);
}

static __device__ __forceinline__ uint32_t smem_u32(const void* p) {
    uint32_t a;
    asm("{ .reg .u64 t; cvta.to.shared.u64 t, %1; cvt.u32.u64 %0, t; }" : "=r"(a) : "l"(p));
    return a;
}

__device__ __forceinline__ unsigned pack_bf16(float lo, float hi) {
    // result low 16 bits = bf16(lo), high = bf16(hi)
    unsigned r;
    asm("cvt.rn.bf16x2.f32 %0, %1, %2;" : "=r"(r) : "f"(hi), "f"(lo));
    return r;
}
// split 8 consecutive fp32 values into hi/lo bf16x2 quads (memory order preserved)
__device__ __forceinline__ void split8(const float* v, uint4& hi, uint4& lo) {
    unsigned h[4], l[4];
#pragma unroll
    for (int g = 0; g < 4; g++) {
        float a0 = v[2 * g], a1 = v[2 * g + 1];
        unsigned p = pack_bf16(a0, a1);
        float h0 = __uint_as_float(p << 16);
        float h1 = __uint_as_float(p & 0xffff0000u);
        h[g] = p;
        l[g] = pack_bf16(a0 - h0, a1 - h1);
    }
    hi = make_uint4(h[0], h[1], h[2], h[3]);
    lo = make_uint4(l[0], l[1], l[2], l[3]);
}

__device__ __forceinline__ void ldsm4(uint32_t addr, uint32_t* r) {
    asm volatile("ldmatrix.sync.aligned.m8n8.x4.shared.b16 {%0,%1,%2,%3}, [%4];"
                 : "=r"(r[0]), "=r"(r[1]), "=r"(r[2]), "=r"(r[3]) : "r"(addr));
}

__device__ __forceinline__ void mma16816(float* c, const uint32_t* a, uint32_t b0, uint32_t b1) {
    asm volatile(
        "mma.sync.aligned.m16n8k16.row.col.f32.bf16.bf16.f32 "
        "{%0,%1,%2,%3}, {%4,%5,%6,%7}, {%8,%9}, {%0,%1,%2,%3};"
        : "+f"(c[0]), "+f"(c[1]), "+f"(c[2]), "+f"(c[3])
        : "r"(a[0]), "r"(a[1]), "r"(a[2]), "r"(a[3]), "r"(b0), "r"(b1));
}

// SMEM layout of the tensor kernel (byte offsets from a 1024-aligned base)
// Double-buffered tiles: buffer = 64KB (AHI/ALO/BHI/BLO 16KB each), x2.
#define BUFSZ   65536
#define OFF_AHI 0
#define OFF_ALO 16384
#define OFF_BHI 32768
#define OFF_BLO 49152
#define OFF_CST (2 * BUFSZ)
#define SMEM_MMA (OFF_CST + 512 + 1024)   // 132608 bytes incl. alignment slack

// ---------------- tiny kernels ----------------
__global__ void zero_kernel() {
    int i = blockIdx.x * 256 + threadIdx.x;
    if (i < 2368) { g_sum[i] = 0.f; g_sq[i] = 0.f; }
    if (i < BATCH * 1024) g_max5[i] = 0u;  // 0 < fmap(any finite float)
}

__global__ void finalize_kernel(const float* __restrict__ s, const float* __restrict__ q,
                                float* __restrict__ mean, float* __restrict__ rstd, int C) {
    int i = blockIdx.x * 64 + threadIdx.x;
    if (i < C) {
        float m = s[i] * (1.0f / 32768.0f);
        float v = q[i] * (1.0f / 32768.0f) - m * m;
        mean[i] = m;
        rstd[i] = rsqrtf(v + EPS_BN);
    }
}

// const6[b][o] = sum_{i in [0,1024)} phi(tanh(BN5(max5[b][i]))) . w6[64+i][o][:]
__global__ void const6_kernel(const float* __restrict__ w6) {
    __shared__ float sb[4][256][4];   // 16KB staged basis
    const int b0 = blockIdx.y * 4;
    const int o = blockIdx.x * 64 + threadIdx.x;
    const float* mean5 = &g_mean[320];
    const float* rstd5 = &g_rstd[320];
    float acc[4] = {0.f, 0.f, 0.f, 0.f};
    for (int i0 = 0; i0 < 1024; i0 += 256) {
        for (int e = threadIdx.x; e < 1024; e += 64) {
            int bj = e >> 8, i = e & 255;
            float f = funmap(g_max5[(b0 + bj) * 1024 + i0 + i]);
            float t = fast_tanh((f - mean5[i0 + i]) * rstd5[i0 + i]);
            float p0, p1, p2, p3;
            jacobi4(t, p0, p1, p2, p3);
            sb[bj][i][0] = p0; sb[bj][i][1] = p1;
            sb[bj][i][2] = p2; sb[bj][i][3] = p3;
        }
        __syncthreads();
#pragma unroll 4
        for (int i = 0; i < 256; i++) {
            float4 wv = *reinterpret_cast<const float4*>(&w6[((size_t)(64 + i0 + i) * 512 + o) * 4]);
#pragma unroll
            for (int bj = 0; bj < 4; bj++)
                acc[bj] += sb[bj][i][0] * wv.x + sb[bj][i][1] * wv.y +
                           sb[bj][i][2] * wv.z + sb[bj][i][3] * wv.w;
        }
        __syncthreads();
    }
#pragma unroll
    for (int bj = 0; bj < 4; bj++) g_const6[(b0 + bj) * 512 + o] = acc[bj];
}

// ======================= split-bf16 HMMA KAN GEMM, double-buffered =======================
// BM=128 x BN=128, BK=64 (16 channels x 4 bases), 256 threads (8 warps, 2Mx4N grid).
// D = Ah*Bh^T + Ah*Bl^T + Al*Bh^T in fp32 accumulators via mma.sync.m16n8k16.bf16.
// Pipeline per k-tile: [LDG kt+1] -> [MMA kt] -> [convert+STS kt+1] -> sync.
// Requires C_in % 16 == 0, C_out % 128 == 0. BN applied to input (mean/rstd).
template <bool MAXPOOL, bool HASCONST>
__global__ __launch_bounds__(256)
void kan_mma(const float* __restrict__ in, const float* __restrict__ w,
             const float* __restrict__ mean, const float* __restrict__ rstd,
             float* __restrict__ out, float* __restrict__ ssum, float* __restrict__ ssq,
             const float* __restrict__ cst, int C_in, int C_out)
{
    extern __shared__ char dsm[];
    const uint32_t raw32 = smem_u32(dsm);
    const uint32_t ab32 = (raw32 + 1023u) & ~1023u;
    char* ab = dsm + (ab32 - raw32);

    const int tid = threadIdx.x;
    const int lane = tid & 31;
    const int wid = tid >> 5;
    const int m0 = blockIdx.y * 128;
    const int n0 = blockIdx.x * 128;
    const int b = m0 >> 10;             // 128-row tiles never cross batch

    float* cst_s = reinterpret_cast<float*>(ab + OFF_CST);
    if (HASCONST && tid < 128) cst_s[tid] = cst[(size_t)b * C_out + n0 + tid];

    float acc[4][4][4];
#pragma unroll
    for (int mi = 0; mi < 4; mi++)
#pragma unroll
        for (int ni = 0; ni < 4; ni++)
#pragma unroll
            for (int r = 0; r < 4; r++) acc[mi][ni][r] = 0.f;

    // producer thread mapping (A: 2 threads/row x 8 ch; B: 2 ch-halves x 128 cols)
    const int arow = tid >> 1;
    const int achq = (tid & 1) * 8;
    const int bn   = tid & 127;
    const int bchh = (tid >> 7) * 8;
    const size_t chstride = (size_t)C_out * 4;

    // warp MMA mapping
    const int mw = (wid >> 2) * 64;     // 2 warps in M
    const int nw = (wid & 3) * 32;      // 4 warps in N
    const int rof = lane & 15;          // ldmatrix row-within-frag
    const int klo = (lane >> 4) * 16;   // 16B chunk select
    const int rbase = ((rof >> 3) << 10) + ((rof & 7) << 7);
    const int rxor = (rof & 7) << 4;

    float pa[8], pb[32];                // prefetch registers

    auto LDG = [&](int ch0) {
        const size_t abase = (size_t)(m0 + arow) * C_in + ch0 + achq;
        *reinterpret_cast<float4*>(&pa[0]) = *reinterpret_cast<const float4*>(&in[abase]);
        *reinterpret_cast<float4*>(&pa[4]) = *reinterpret_cast<const float4*>(&in[abase + 4]);
        const size_t wb = ((size_t)(ch0 + bchh) * C_out + (n0 + bn)) * 4;
#pragma unroll
        for (int c = 0; c < 8; c++)
            *reinterpret_cast<float4*>(&pb[c * 4]) =
                *reinterpret_cast<const float4*>(&w[wb + (size_t)c * chstride]);
    };

    auto CVT = [&](int ch0, uint32_t bufo) {
        // A: basis expansion -> bf16 hi/lo, SW128
        float vals[32];
#pragma unroll
        for (int j = 0; j < 8; j++) {
            const int cc = ch0 + achq + j;
            float t = fast_tanh((pa[j] - mean[cc]) * rstd[cc]);
            jacobi4(t, vals[j * 4 + 0], vals[j * 4 + 1], vals[j * 4 + 2], vals[j * 4 + 3]);
        }
        {
            const uint32_t offr = ((uint32_t)(arow >> 3) << 10) + ((uint32_t)(arow & 7) << 7);
            const uint32_t rx = (uint32_t)(arow & 7) << 4;
#pragma unroll
            for (int g = 0; g < 4; g++) {
                uint4 hi, lo;
                split8(vals + 8 * g, hi, lo);
                const uint32_t cb = (uint32_t)achq * 8 + g * 16;
                const uint32_t sw = offr + (cb ^ rx);
                *reinterpret_cast<uint4*>(ab + bufo + OFF_AHI + sw) = hi;
                *reinterpret_cast<uint4*>(ab + bufo + OFF_ALO + sw) = lo;
            }
        }
        // B: weights -> bf16 hi/lo, SW128 (rows = output col)
        {
            const uint32_t offr = ((uint32_t)(bn >> 3) << 10) + ((uint32_t)(bn & 7) << 7);
            const uint32_t rx = (uint32_t)(bn & 7) << 4;
#pragma unroll
            for (int cp = 0; cp < 4; cp++) {
                uint4 hi, lo;
                split8(&pb[cp * 8], hi, lo);
                const uint32_t cb = (uint32_t)bchh * 8 + cp * 16;
                const uint32_t sw = offr + (cb ^ rx);
                *reinterpret_cast<uint4*>(ab + bufo + OFF_BHI + sw) = hi;
                *reinterpret_cast<uint4*>(ab + bufo + OFF_BLO + sw) = lo;
            }
        }
    };

    const int numKT = C_in >> 4;

    // prologue: fill buffer 0
    LDG(0);
    CVT(0, 0u);
    __syncthreads();

    for (int kt = 0; kt < numKT; kt++) {
        // prefetch next tile's gmem data before issuing MMAs (hides L2 latency)
        if (kt + 1 < numKT) LDG((kt + 1) * 16);

        const uint32_t bb = ab32 + ((kt & 1) ? (uint32_t)BUFSZ : 0u);
        const uint32_t AH = bb + OFF_AHI, AL = bb + OFF_ALO;
        const uint32_t BH = bb + OFF_BHI, BL = bb + OFF_BLO;

#pragma unroll
        for (int ks = 0; ks < 4; ks++) {
            const uint32_t kb = ks * 32;
            uint32_t ah[4][4];
#pragma unroll
            for (int mi = 0; mi < 4; mi++) {
                const uint32_t off = ((uint32_t)((mw + mi * 16) >> 3) << 10) + rbase
                                     + ((kb + klo) ^ rxor);
                ldsm4(AH + off, ah[mi]);
            }
            uint32_t bh[2][4], bl[2][4];
#pragma unroll
            for (int nj = 0; nj < 2; nj++) {
                const uint32_t off = ((uint32_t)((nw + nj * 16) >> 3) << 10) + rbase
                                     + ((kb + klo) ^ rxor);
                ldsm4(BH + off, bh[nj]);
                ldsm4(BL + off, bl[nj]);
            }
#pragma unroll
            for (int mi = 0; mi < 4; mi++)
#pragma unroll
                for (int ni = 0; ni < 4; ni++) {
                    const int nj = ni >> 1, s = ni & 1;
                    mma16816(acc[mi][ni], ah[mi], bh[nj][s], bh[nj][s + 2]);
                    mma16816(acc[mi][ni], ah[mi], bl[nj][s], bl[nj][s + 2]);
                }
            uint32_t al[4][4];
#pragma unroll
            for (int mi = 0; mi < 4; mi++) {
                const uint32_t off = ((uint32_t)((mw + mi * 16) >> 3) << 10) + rbase
                                     + ((kb + klo) ^ rxor);
                ldsm4(AL + off, al[mi]);
            }
#pragma unroll
            for (int mi = 0; mi < 4; mi++)
#pragma unroll
                for (int ni = 0; ni < 4; ni++) {
                    const int nj = ni >> 1, s = ni & 1;
                    mma16816(acc[mi][ni], al[mi], bh[nj][s], bh[nj][s + 2]);
                }
        }

        // convert + store next tile while the tensor pipe drains this tile's MMAs
        if (kt + 1 < numKT) CVT((kt + 1) * 16, ((kt + 1) & 1) ? (uint32_t)BUFSZ : 0u);
        __syncthreads();
    }

    // ---- epilogue: frags -> smem [128][130] fp32, then coalesced store + stats ----
    float* scr = reinterpret_cast<float*>(ab);
#pragma unroll
    for (int mi = 0; mi < 4; mi++)
#pragma unroll
        for (int ni = 0; ni < 4; ni++)
#pragma unroll
            for (int r = 0; r < 4; r++) {
                const int ml = mw + mi * 16 + (lane >> 2) + (r >> 1) * 8;
                const int nl = nw + ni * 8 + (lane & 3) * 2 + (r & 1);
                float v = acc[mi][ni][r];
                if (HASCONST) v += cst_s[nl];
                scr[ml * 130 + nl] = v;
            }
    __syncthreads();

    if (!MAXPOOL) {
#pragma unroll 4
        for (int i = 0; i < 16; i++) {
            const int r = wid * 16 + i;
            const float* row = &scr[r * 130 + lane * 4];
            *reinterpret_cast<float4*>(&out[(size_t)(m0 + r) * C_out + n0 + lane * 4]) =
                make_float4(row[0], row[1], row[2], row[3]);
        }
    }
    if (tid < 128) {
        float s = 0.f, q = 0.f, mx = -3.4e38f;
        for (int r = 0; r < 128; r++) {
            float v = scr[r * 130 + tid];
            s += v; q += v * v;
            if (MAXPOOL) mx = fmaxf(mx, v);
        }
        atomicAdd(&ssum[n0 + tid], s);
        atomicAdd(&ssq[n0 + tid], q);
        if (MAXPOOL) atomicMax(&g_max5[b * 1024 + n0 + tid], fmap(mx));
    }
}

// ======================= scalar GEMM (edge layers: L1, L2, L3, L10) =======================
template <bool FIRST, bool LAST>
__global__ __launch_bounds__(256) void kan_gemm(
    const float* __restrict__ in, const float* __restrict__ w,
    const float* __restrict__ mean, const float* __restrict__ rstd,
    float* __restrict__ out, float* __restrict__ ssum, float* __restrict__ ssq,
    int C_in, int C_out)
{
    __shared__ float As[32][128];
    __shared__ float Bs[32][64];
    __shared__ float redS[16][64];
    __shared__ float redQ[16][64];

    const int tid = threadIdx.x;
    const int tcol = tid & 15, trow = tid >> 4;
    const int m0 = blockIdx.y * 128;
    const int n0 = blockIdx.x * 64;

    float acc[8][4];
#pragma unroll
    for (int r = 0; r < 8; r++)
#pragma unroll
        for (int c = 0; c < 4; c++) acc[r][c] = 0.f;

    const int numKT = (C_in + 7) >> 3;
    for (int kt = 0; kt < numKT; kt++) {
        const int ch0 = kt * 8;
        if (FIRST) {
            const int ch = tid & 7;
            const int rb = tid >> 3;
#pragma unroll
            for (int p = 0; p < 4; p++) {
                int row = rb + p * 32;
                float p0 = 0.f, p1 = 0.f, p2 = 0.f, p3 = 0.f;
                if (ch0 + ch < C_in) {
                    int m = m0 + row;
                    float v = in[(m >> 10) * (2 * NPTS) + (ch0 + ch) * NPTS + (m & (NPTS - 1))];
                    float t = fast_tanh(v);
                    jacobi4(t, p0, p1, p2, p3);
                }
                int k = ch * 4;
                As[k + 0][row] = p0; As[k + 1][row] = p1;
                As[k + 2][row] = p2; As[k + 3][row] = p3;
            }
        } else {
            const int row = tid >> 1;
            const int chq = (tid & 1) * 4;
            const float4 v4 =
                *reinterpret_cast<const float4*>(&in[(size_t)(m0 + row) * C_in + ch0 + chq]);
            const float vv[4] = {v4.x, v4.y, v4.z, v4.w};
#pragma unroll
            for (int j = 0; j < 4; j++) {
                int cc = ch0 + chq + j;
                float t = fast_tanh((vv[j] - mean[cc]) * rstd[cc]);
                float p0, p1, p2, p3;
                jacobi4(t, p0, p1, p2, p3);
                int k = (chq + j) * 4;
                As[k + 0][row] = p0; As[k + 1][row] = p1;
                As[k + 2][row] = p2; As[k + 3][row] = p3;
            }
        }
#pragma unroll
        for (int p = 0; p < 2; p++) {
            int f = tid + p * 256;
            int ch = f >> 6;
            int o = f & 63;
            int cc = ch0 + ch;
            int col = n0 + o;
            float4 wv = make_float4(0.f, 0.f, 0.f, 0.f);
            if (cc < C_in && col < C_out)
                wv = *reinterpret_cast<const float4*>(&w[((size_t)cc * C_out + col) * 4]);
            int k = ch * 4;
            Bs[k + 0][o] = wv.x; Bs[k + 1][o] = wv.y;
            Bs[k + 2][o] = wv.z; Bs[k + 3][o] = wv.w;
        }
        __syncthreads();

#pragma unroll
        for (int k = 0; k < 32; k++) {
            float a[8], bv[4];
#pragma unroll
            for (int r = 0; r < 8; r++) a[r] = As[k][trow * 8 + r];
#pragma unroll
            for (int c = 0; c < 4; c++) bv[c] = Bs[k][tcol * 4 + c];
#pragma unroll
            for (int r = 0; r < 8; r++)
#pragma unroll
                for (int c = 0; c < 4; c++) acc[r][c] = fmaf(a[r], bv[c], acc[r][c]);
        }
        __syncthreads();
    }

    if (LAST) {
#pragma unroll
        for (int r = 0; r < 8; r++) {
            int m = m0 + trow * 8 + r;
            int bb = m >> 10, n = m & (NPTS - 1);
#pragma unroll
            for (int c = 0; c < 4; c++) {
                int col = n0 + tcol * 4 + c;
                if (col < C_out) out[((size_t)bb * C_out + col) * NPTS + n] = acc[r][c];
            }
        }
    } else {
#pragma unroll
        for (int r = 0; r < 8; r++) {
            size_t m = m0 + trow * 8 + r;
            float4 v = make_float4(acc[r][0], acc[r][1], acc[r][2], acc[r][3]);
            *reinterpret_cast<float4*>(&out[m * C_out + n0 + tcol * 4]) = v;
        }
        float s[4] = {0, 0, 0, 0}, q[4] = {0, 0, 0, 0};
#pragma unroll
        for (int r = 0; r < 8; r++)
#pragma unroll
            for (int c = 0; c < 4; c++) {
                s[c] += acc[r][c];
                q[c] += acc[r][c] * acc[r][c];
            }
#pragma unroll
        for (int c = 0; c < 4; c++) {
            redS[trow][tcol * 4 + c] = s[c];
            redQ[trow][tcol * 4 + c] = q[c];
        }
        __syncthreads();
        if (tid < 64 && (n0 + tid) < C_out) {
            float ts = 0.f, tq = 0.f;
#pragma unroll
            for (int r = 0; r < 16; r++) { ts += redS[r][tid]; tq += redQ[r][tid]; }
            atomicAdd(&ssum[n0 + tid], ts);
            atomicAdd(&ssq[n0 + tid], tq);
        }
    }
}

// ---------------- launch ----------------
static inline int cdiv(int a, int b) { return (a + b - 1) / b; }

extern "C" void kernel_launch(void* const* d_in, const int* in_sizes, int n_in,
                              void* d_out, int out_size) {
    (void)in_sizes; (void)n_in; (void)out_size;
    const float* x   = (const float*)d_in[0];
    const float* w1  = (const float*)d_in[1];
    const float* w2  = (const float*)d_in[2];
    const float* w3  = (const float*)d_in[3];
    const float* w4  = (const float*)d_in[4];
    const float* w5  = (const float*)d_in[5];
    const float* w6  = (const float*)d_in[6];
    const float* w7  = (const float*)d_in[7];
    const float* w8  = (const float*)d_in[8];
    const float* w9  = (const float*)d_in[9];
    const float* w10 = (const float*)d_in[10];
    float* outp = (float*)d_out;

    float *z1, *z2, *z3, *z4, *z6, *z7, *z8, *z9;
    float *sum, *sq, *mean, *rstd, *cst6;
    cudaGetSymbolAddress((void**)&z1, g_z1);
    cudaGetSymbolAddress((void**)&z2, g_z2);
    cudaGetSymbolAddress((void**)&z3, g_z3);
    cudaGetSymbolAddress((void**)&z4, g_z4);
    cudaGetSymbolAddress((void**)&z6, g_z6);
    cudaGetSymbolAddress((void**)&z7, g_z7);
    cudaGetSymbolAddress((void**)&z8, g_z8);
    cudaGetSymbolAddress((void**)&z9, g_z9);
    cudaGetSymbolAddress((void**)&sum, g_sum);
    cudaGetSymbolAddress((void**)&sq, g_sq);
    cudaGetSymbolAddress((void**)&mean, g_mean);
    cudaGetSymbolAddress((void**)&rstd, g_rstd);
    cudaGetSymbolAddress((void**)&cst6, g_const6);

    cudaFuncSetAttribute(kan_mma<false, false>, cudaFuncAttributeMaxDynamicSharedMemorySize, SMEM_MMA);
    cudaFuncSetAttribute(kan_mma<true, false>,  cudaFuncAttributeMaxDynamicSharedMemorySize, SMEM_MMA);
    cudaFuncSetAttribute(kan_mma<false, true>,  cudaFuncAttributeMaxDynamicSharedMemorySize, SMEM_MMA);

    zero_kernel<<<cdiv(BATCH * 1024, 256), 256>>>();

    // L1: x(2) -> z1(64)   [scalar FIRST]
    kan_gemm<true, false><<<dim3(1, 256), 256>>>(
        x, w1, nullptr, nullptr, z1, sum + 0, sq + 0, 2, 64);
    finalize_kernel<<<1, 64>>>(sum + 0, sq + 0, mean + 0, rstd + 0, 64);

    // L2: z1(64) -> z2(64)   [scalar]
    kan_gemm<false, false><<<dim3(1, 256), 256>>>(
        z1, w2, mean + 0, rstd + 0, z2, sum + 64, sq + 64, 64, 64);
    finalize_kernel<<<1, 64>>>(sum + 64, sq + 64, mean + 64, rstd + 64, 64);

    // L3: z2(64) -> z3(64)   [scalar]
    kan_gemm<false, false><<<dim3(1, 256), 256>>>(
        z2, w3, mean + 64, rstd + 64, z3, sum + 128, sq + 128, 64, 64);
    finalize_kernel<<<1, 64>>>(sum + 128, sq + 128, mean + 128, rstd + 128, 64);

    // L4: z3(64) -> z4(128)   [HMMA]
    kan_mma<false, false><<<dim3(1, 256), 256, SMEM_MMA>>>(
        z3, w4, mean + 128, rstd + 128, z4, sum + 192, sq + 192, nullptr, 64, 128);
    finalize_kernel<<<2, 64>>>(sum + 192, sq + 192, mean + 192, rstd + 192, 128);

    // L5: z4(128) -> (maxpool + stats only, z5 never stored)   [HMMA, MAXPOOL]
    kan_mma<true, false><<<dim3(8, 256), 256, SMEM_MMA>>>(
        z4, w5, mean + 192, rstd + 192, nullptr, sum + 320, sq + 320, nullptr, 128, 1024);
    finalize_kernel<<<16, 64>>>(sum + 320, sq + 320, mean + 320, rstd + 320, 1024);

    // gf constant contribution to layer 6
    const6_kernel<<<dim3(8, 8), 64>>>(w6);

    // L6: local z2(64) -> z6(512), + const6   [HMMA, HASCONST]
    kan_mma<false, true><<<dim3(4, 256), 256, SMEM_MMA>>>(
        z2, w6, mean + 64, rstd + 64, z6, sum + 1344, sq + 1344, cst6, 64, 512);
    finalize_kernel<<<8, 64>>>(sum + 1344, sq + 1344, mean + 1344, rstd + 1344, 512);

    // L7: z6(512) -> z7(256)   [HMMA]
    kan_mma<false, false><<<dim3(2, 256), 256, SMEM_MMA>>>(
        z6, w7, mean + 1344, rstd + 1344, z7, sum + 1856, sq + 1856, nullptr, 512, 256);
    finalize_kernel<<<4, 64>>>(sum + 1856, sq + 1856, mean + 1856, rstd + 1856, 256);

    // L8: z7(256) -> z8(128)   [HMMA]
    kan_mma<false, false><<<dim3(1, 256), 256, SMEM_MMA>>>(
        z7, w8, mean + 1856, rstd + 1856, z8, sum + 2112, sq + 2112, nullptr, 256, 128);
    finalize_kernel<<<2, 64>>>(sum + 2112, sq + 2112, mean + 2112, rstd + 2112, 128);

    // L9: z8(128) -> z9(128)   [HMMA]
    kan_mma<false, false><<<dim3(1, 256), 256, SMEM_MMA>>>(
        z8, w9, mean + 2112, rstd + 2112, z9, sum + 2240, sq + 2240, nullptr, 128, 128);
    finalize_kernel<<<2, 64>>>(sum + 2240, sq + 2240, mean + 2240, rstd + 2240, 128);

    // L10: z9(128) -> out (B, 3, N), no BN   [scalar LAST]
    kan_gemm<false, true><<<dim3(1, 256), 256>>>(
        z9, w10, mean + 2240, rstd + 2240, outp, nullptr, nullptr, 128, 3);
}

// round 12
// speedup vs baseline: 1.0012x; 1.0012x over previous
#include <cuda_runtime.h>
#include <cstddef>
#include <cstdint>

#define NPTS 1024
#define BATCH 32
#define MTOT 32768
#define EPS_BN 1e-5f

// ---------------- static scratch (no allocations allowed) ----------------
__device__ float g_z1[(size_t)MTOT * 64];
__device__ float g_z2[(size_t)MTOT * 64];
__device__ float g_z3[(size_t)MTOT * 64];
__device__ float g_z4[(size_t)MTOT * 128];
// z5 is never materialized: max-pool + stats are fused into the L5 GEMM epilogue
__device__ float g_z6[(size_t)MTOT * 512];
__device__ float g_z7[(size_t)MTOT * 256];
__device__ float g_z8[(size_t)MTOT * 128];
__device__ float g_z9[(size_t)MTOT * 128];

// per-channel stats, packed by layer offset:
// L1:0(64) L2:64 L3:128 L4:192(128) L5:320(1024) L6:1344(512) L7:1856(256) L8:2112(128) L9:2240(128) -> 2368
__device__ float g_sum[2368];
__device__ float g_sq[2368];
__device__ float g_mean[2368];
__device__ float g_rstd[2368];

__device__ unsigned g_max5[BATCH * 1024];   // order-monotone uint-mapped float max
__device__ float g_const6[BATCH * 512];     // per-batch gf contribution to layer 6

// ---------------- helpers ----------------
__device__ __forceinline__ float fast_tanh(float x) {
    // tanh(x) = 1 - 2/(exp(2x)+1); ex2.approx + rcp.approx, rel err ~1e-6
    float e, r;
    asm("ex2.approx.f32 %0, %1;" : "=f"(e) : "f"(x * 2.8853900817779268f)); // 2*log2(e)
    asm("rcp.approx.f32 %0, %1;" : "=f"(r) : "f"(e + 1.0f));
    return 1.0f - 2.0f * r;
}

// Jacobi polys, degree 3, a=b=1 (exact constants from the reference recurrence)
__device__ __forceinline__ void jacobi4(float t, float& p0, float& p1, float& p2, float& p3) {
    p0 = 1.0f;
    p1 = 2.0f * t;
    p2 = 1.875f * t * p1 - 0.75f;
    p3 = 1.8666666666666667f * t * p2 - 0.8f * p1;
}

__device__ __forceinline__ unsigned fmap(float f) {
    unsigned u = __float_as_uint(f);
    return (u & 0x80000000u) ? ~u : (u | 0x80000000u);
}
__device__ __forceinline__ float funmap(unsigned u) {
    return (u & 0x80000000u) ? __uint_as_float(u & 0x7fffffffu) : __uint_as_float(~u);
}

static __device__ __forceinline__ uint32_t smem_u32(const void* p) {
    uint32_t a;
    asm("{ .reg .u64 t; cvta.to.shared.u64 t, %1; cvt.u32.u64 %0, t; }" : "=r"(a) : "l"(p));
    return a;
}

__device__ __forceinline__ unsigned pack_bf16(float lo, float hi) {
    // result low 16 bits = bf16(lo), high = bf16(hi)
    unsigned r;
    asm("cvt.rn.bf16x2.f32 %0, %1, %2;" : "=r"(r) : "f"(hi), "f"(lo));
    return r;
}
// split 8 consecutive fp32 values into hi/lo bf16x2 quads (memory order preserved)
__device__ __forceinline__ void split8(const float* v, uint4& hi, uint4& lo) {
    unsigned h[4], l[4];
#pragma unroll
    for (int g = 0; g < 4; g++) {
        float a0 = v[2 * g], a1 = v[2 * g + 1];
        unsigned p = pack_bf16(a0, a1);
        float h0 = __uint_as_float(p << 16);
        float h1 = __uint_as_float(p & 0xffff0000u);
        h[g] = p;
        l[g] = pack_bf16(a0 - h0, a1 - h1);
    }
    hi = make_uint4(h[0], h[1], h[2], h[3]);
    lo = make_uint4(l[0], l[1], l[2], l[3]);
}

__device__ __forceinline__ void ldsm4(uint32_t addr, uint32_t* r) {
    asm volatile("ldmatrix.sync.aligned.m8n8.x4.shared.b16 {%0,%1,%2,%3}, [%4];"
                 : "=r"(r[0]), "=r"(r[1]), "=r"(r[2]), "=r"(r[3]) : "r"(addr));
}

__device__ __forceinline__ void mma16816(float* c, const uint32_t* a, uint32_t b0, uint32_t b1) {
    asm volatile(
        "mma.sync.aligned.m16n8k16.row.col.f32.bf16.bf16.f32 "
        "{%0,%1,%2,%3}, {%4,%5,%6,%7}, {%8,%9}, {%0,%1,%2,%3};"
        : "+f"(c[0]), "+f"(c[1]), "+f"(c[2]), "+f"(c[3])
        : "r"(a[0]), "r"(a[1]), "r"(a[2]), "r"(a[3]), "r"(b0), "r"(b1));
}

// SMEM layout of the tensor kernel (byte offsets from a 1024-aligned base)
// BM=128 x BN=64 tile: A hi/lo 16KB each, B hi/lo 8KB each -> 48KB; 2 CTAs/SM.
#define OFF_AHI 0
#define OFF_ALO 16384
#define OFF_BHI 32768
#define OFF_BLO 40960
#define OFF_CST 49152
#define SMEM_MMA (OFF_CST + 256 + 1024)

// ---------------- tiny kernels ----------------
__global__ void zero_kernel() {
    int i = blockIdx.x * 256 + threadIdx.x;
    if (i < 2368) { g_sum[i] = 0.f; g_sq[i] = 0.f; }
    if (i < BATCH * 1024) g_max5[i] = 0u;  // 0 < fmap(any finite float)
}

__global__ void finalize_kernel(const float* __restrict__ s, const float* __restrict__ q,
                                float* __restrict__ mean, float* __restrict__ rstd, int C) {
    int i = blockIdx.x * 64 + threadIdx.x;
    if (i < C) {
        float m = s[i] * (1.0f / 32768.0f);
        float v = q[i] * (1.0f / 32768.0f) - m * m;
        mean[i] = m;
        rstd[i] = rsqrtf(v + EPS_BN);
    }
}

// const6[b][o] = sum_{i in [0,1024)} phi(tanh(BN5(max5[b][i]))) . w6[64+i][o][:]
__global__ void const6_kernel(const float* __restrict__ w6) {
    __shared__ float sb[4][256][4];   // 16KB staged basis
    const int b0 = blockIdx.y * 4;
    const int o = blockIdx.x * 64 + threadIdx.x;
    const float* mean5 = &g_mean[320];
    const float* rstd5 = &g_rstd[320];
    float acc[4] = {0.f, 0.f, 0.f, 0.f};
    for (int i0 = 0; i0 < 1024; i0 += 256) {
        for (int e = threadIdx.x; e < 1024; e += 64) {
            int bj = e >> 8, i = e & 255;
            float f = funmap(g_max5[(b0 + bj) * 1024 + i0 + i]);
            float t = fast_tanh((f - mean5[i0 + i]) * rstd5[i0 + i]);
            float p0, p1, p2, p3;
            jacobi4(t, p0, p1, p2, p3);
            sb[bj][i][0] = p0; sb[bj][i][1] = p1;
            sb[bj][i][2] = p2; sb[bj][i][3] = p3;
        }
        __syncthreads();
#pragma unroll 4
        for (int i = 0; i < 256; i++) {
            float4 wv = *reinterpret_cast<const float4*>(&w6[((size_t)(64 + i0 + i) * 512 + o) * 4]);
#pragma unroll
            for (int bj = 0; bj < 4; bj++)
                acc[bj] += sb[bj][i][0] * wv.x + sb[bj][i][1] * wv.y +
                           sb[bj][i][2] * wv.z + sb[bj][i][3] * wv.w;
        }
        __syncthreads();
    }
#pragma unroll
    for (int bj = 0; bj < 4; bj++) g_const6[(b0 + bj) * 512 + o] = acc[bj];
}

// ======================= split-bf16 HMMA KAN GEMM (heavy layers) =======================
// BM=128 x BN=64, BK=64 (16 channels x 4 bases), 256 threads (8 warps, 4Mx2N grid).
// D = Ah*Bh^T + Ah*Bl^T + Al*Bh^T in fp32 accumulators via mma.sync.m16n8k16.bf16.
// 2 CTAs/SM (launch_bounds + 50KB smem): producer phase of one CTA overlaps the
// MMA phase of the other -> tensor-pipe overlap without register prefetch.
// Requires C_in % 16 == 0, C_out % 64 == 0. BN applied to input (mean/rstd).
template <bool MAXPOOL, bool HASCONST>
__global__ __launch_bounds__(256, 2)
void kan_mma(const float* __restrict__ in, const float* __restrict__ w,
             const float* __restrict__ mean, const float* __restrict__ rstd,
             float* __restrict__ out, float* __restrict__ ssum, float* __restrict__ ssq,
             const float* __restrict__ cst, int C_in, int C_out)
{
    extern __shared__ char dsm[];
    const uint32_t raw32 = smem_u32(dsm);
    const uint32_t ab32 = (raw32 + 1023u) & ~1023u;
    char* ab = dsm + (ab32 - raw32);

    const int tid = threadIdx.x;
    const int lane = tid & 31;
    const int wid = tid >> 5;
    const int m0 = blockIdx.y * 128;
    const int n0 = blockIdx.x * 64;
    const int b = m0 >> 10;             // 128-row tiles never cross batch

    float* cst_s = reinterpret_cast<float*>(ab + OFF_CST);
    if (HASCONST && tid < 64) cst_s[tid] = cst[(size_t)b * C_out + n0 + tid];

    float acc[2][4][4];
#pragma unroll
    for (int mi = 0; mi < 2; mi++)
#pragma unroll
        for (int ni = 0; ni < 4; ni++)
#pragma unroll
            for (int r = 0; r < 4; r++) acc[mi][ni][r] = 0.f;

    // producer thread mapping
    const int arow = tid >> 1;          // A: 2 threads/row, 8 channels each
    const int achq = (tid & 1) * 8;
    const int bn = tid & 63;            // B: 4 thread-groups x 4 channels, 64 cols
    const int bchq = (tid >> 6) * 4;

    // warp MMA mapping: 4 warps in M (32 rows), 2 warps in N (32 cols)
    const int mw = (wid >> 1) * 32;
    const int nw = (wid & 1) * 32;
    const int rof = lane & 15;
    const int klo = (lane >> 4) * 16;
    const int rbase = ((rof >> 3) << 10) + ((rof & 7) << 7);
    const int rxor = (rof & 7) << 4;

    const uint32_t AH = ab32 + OFF_AHI, AL = ab32 + OFF_ALO;
    const uint32_t BHa = ab32 + OFF_BHI, BLa = ab32 + OFF_BLO;

    const int numKT = C_in >> 4;
    for (int kt = 0; kt < numKT; kt++) {
        const int ch0 = kt * 16;

        // ---- A producer: 128 rows x 16 channels -> basis -> bf16 hi/lo, SW128 ----
        {
            const size_t abase = (size_t)(m0 + arow) * C_in + ch0 + achq;
            const float4 v4a = *reinterpret_cast<const float4*>(&in[abase]);
            const float4 v4b = *reinterpret_cast<const float4*>(&in[abase + 4]);
            const float vv[8] = {v4a.x, v4a.y, v4a.z, v4a.w, v4b.x, v4b.y, v4b.z, v4b.w};
            const uint32_t offr = ((uint32_t)(arow >> 3) << 10) + ((uint32_t)(arow & 7) << 7);
            const uint32_t rx = (uint32_t)(arow & 7) << 4;
#pragma unroll
            for (int p = 0; p < 4; p++) {    // channel pairs -> small live set
                const int c0 = achq + 2 * p;
                float t0 = fast_tanh((vv[2 * p] - mean[ch0 + c0]) * rstd[ch0 + c0]);
                float t1 = fast_tanh((vv[2 * p + 1] - mean[ch0 + c0 + 1]) * rstd[ch0 + c0 + 1]);
                float v8[8];
                jacobi4(t0, v8[0], v8[1], v8[2], v8[3]);
                jacobi4(t1, v8[4], v8[5], v8[6], v8[7]);
                uint4 hi, lo;
                split8(v8, hi, lo);
                const uint32_t sw = offr + (((uint32_t)c0 * 8) ^ rx);
                *reinterpret_cast<uint4*>(ab + OFF_AHI + sw) = hi;
                *reinterpret_cast<uint4*>(ab + OFF_ALO + sw) = lo;
            }
        }

        // ---- B producer: w[ch][n0+n][0..3] -> bf16 hi/lo, SW128 (rows = out col) ----
        {
            const uint32_t offr = ((uint32_t)(bn >> 3) << 10) + ((uint32_t)(bn & 7) << 7);
            const uint32_t rx = (uint32_t)(bn & 7) << 4;
            const size_t chstride = (size_t)C_out * 4;
            const size_t wb = ((size_t)(ch0 + bchq) * C_out + (n0 + bn)) * 4;
#pragma unroll
            for (int p = 0; p < 2; p++) {    // channel pairs
                float4 w0 = *reinterpret_cast<const float4*>(&w[wb + (size_t)(2 * p) * chstride]);
                float4 w1 = *reinterpret_cast<const float4*>(&w[wb + (size_t)(2 * p + 1) * chstride]);
                const float v8[8] = {w0.x, w0.y, w0.z, w0.w, w1.x, w1.y, w1.z, w1.w};
                uint4 hi, lo;
                split8(v8, hi, lo);
                const uint32_t sw = offr + (((uint32_t)(bchq + 2 * p) * 8) ^ rx);
                *reinterpret_cast<uint4*>(ab + OFF_BHI + sw) = hi;
                *reinterpret_cast<uint4*>(ab + OFF_BLO + sw) = lo;
            }
        }
        __syncthreads();

        // ---- HMMA: 4 k16 chunks x (AhBh + AhBl + AlBh) ----
#pragma unroll
        for (int ks = 0; ks < 4; ks++) {
            const uint32_t kb = ks * 32;
            uint32_t ah[2][4];
#pragma unroll
            for (int mi = 0; mi < 2; mi++) {
                const uint32_t off = ((uint32_t)((mw + mi * 16) >> 3) << 10) + rbase
                                     + ((kb + klo) ^ rxor);
                ldsm4(AH + off, ah[mi]);
            }
            uint32_t bh[2][4], bl[2][4];
#pragma unroll
            for (int nj = 0; nj < 2; nj++) {
                const uint32_t off = ((uint32_t)((nw + nj * 16) >> 3) << 10) + rbase
                                     + ((kb + klo) ^ rxor);
                ldsm4(BHa + off, bh[nj]);
                ldsm4(BLa + off, bl[nj]);
            }
#pragma unroll
            for (int mi = 0; mi < 2; mi++)
#pragma unroll
                for (int ni = 0; ni < 4; ni++) {
                    const int nj = ni >> 1, s = ni & 1;
                    mma16816(acc[mi][ni], ah[mi], bh[nj][s], bh[nj][s + 2]);
                    mma16816(acc[mi][ni], ah[mi], bl[nj][s], bl[nj][s + 2]);
                }
            uint32_t al[2][4];
#pragma unroll
            for (int mi = 0; mi < 2; mi++) {
                const uint32_t off = ((uint32_t)((mw + mi * 16) >> 3) << 10) + rbase
                                     + ((kb + klo) ^ rxor);
                ldsm4(AL + off, al[mi]);
            }
#pragma unroll
            for (int mi = 0; mi < 2; mi++)
#pragma unroll
                for (int ni = 0; ni < 4; ni++) {
                    const int nj = ni >> 1, s = ni & 1;
                    mma16816(acc[mi][ni], al[mi], bh[nj][s], bh[nj][s + 2]);
                }
        }
        __syncthreads();
    }

    // ---- epilogue: frags -> smem [128][66] fp32, then coalesced store + stats ----
    float* scr = reinterpret_cast<float*>(ab);
#pragma unroll
    for (int mi = 0; mi < 2; mi++)
#pragma unroll
        for (int ni = 0; ni < 4; ni++)
#pragma unroll
            for (int r = 0; r < 4; r++) {
                const int ml = mw + mi * 16 + (lane >> 2) + (r >> 1) * 8;
                const int nl = nw + ni * 8 + (lane & 3) * 2 + (r & 1);
                float v = acc[mi][ni][r];
                if (HASCONST) v += cst_s[nl];
                scr[ml * 66 + nl] = v;
            }
    __syncthreads();

    if (!MAXPOOL) {
        const int r = tid >> 1;
        const int cg = (tid & 1) * 32;
        const float* row = &scr[r * 66 + cg];
        float4* dst = reinterpret_cast<float4*>(&out[(size_t)(m0 + r) * C_out + n0 + cg]);
#pragma unroll
        for (int g = 0; g < 8; g++)
            dst[g] = make_float4(row[g * 4], row[g * 4 + 1], row[g * 4 + 2], row[g * 4 + 3]);
    }
    if (tid < 64) {
        float s = 0.f, q = 0.f, mx = -3.4e38f;
        for (int r = 0; r < 128; r++) {
            float v = scr[r * 66 + tid];
            s += v; q += v * v;
            if (MAXPOOL) mx = fmaxf(mx, v);
        }
        atomicAdd(&ssum[n0 + tid], s);
        atomicAdd(&ssq[n0 + tid], q);
        if (MAXPOOL) atomicMax(&g_max5[b * 1024 + n0 + tid], fmap(mx));
    }
}

// ======================= scalar GEMM (edge layers: L1, L2, L3, L10) =======================
template <bool FIRST, bool LAST>
__global__ __launch_bounds__(256) void kan_gemm(
    const float* __restrict__ in, const float* __restrict__ w,
    const float* __restrict__ mean, const float* __restrict__ rstd,
    float* __restrict__ out, float* __restrict__ ssum, float* __restrict__ ssq,
    int C_in, int C_out)
{
    __shared__ float As[32][128];
    __shared__ float Bs[32][64];
    __shared__ float redS[16][64];
    __shared__ float redQ[16][64];

    const int tid = threadIdx.x;
    const int tcol = tid & 15, trow = tid >> 4;
    const int m0 = blockIdx.y * 128;
    const int n0 = blockIdx.x * 64;

    float acc[8][4];
#pragma unroll
    for (int r = 0; r < 8; r++)
#pragma unroll
        for (int c = 0; c < 4; c++) acc[r][c] = 0.f;

    const int numKT = (C_in + 7) >> 3;
    for (int kt = 0; kt < numKT; kt++) {
        const int ch0 = kt * 8;
        if (FIRST) {
            const int ch = tid & 7;
            const int rb = tid >> 3;
#pragma unroll
            for (int p = 0; p < 4; p++) {
                int row = rb + p * 32;
                float p0 = 0.f, p1 = 0.f, p2 = 0.f, p3 = 0.f;
                if (ch0 + ch < C_in) {
                    int m = m0 + row;
                    float v = in[(m >> 10) * (2 * NPTS) + (ch0 + ch) * NPTS + (m & (NPTS - 1))];
                    float t = fast_tanh(v);
                    jacobi4(t, p0, p1, p2, p3);
                }
                int k = ch * 4;
                As[k + 0][row] = p0; As[k + 1][row] = p1;
                As[k + 2][row] = p2; As[k + 3][row] = p3;
            }
        } else {
            const int row = tid >> 1;
            const int chq = (tid & 1) * 4;
            const float4 v4 =
                *reinterpret_cast<const float4*>(&in[(size_t)(m0 + row) * C_in + ch0 + chq]);
            const float vv[4] = {v4.x, v4.y, v4.z, v4.w};
#pragma unroll
            for (int j = 0; j < 4; j++) {
                int cc = ch0 + chq + j;
                float t = fast_tanh((vv[j] - mean[cc]) * rstd[cc]);
                float p0, p1, p2, p3;
                jacobi4(t, p0, p1, p2, p3);
                int k = (chq + j) * 4;
                As[k + 0][row] = p0; As[k + 1][row] = p1;
                As[k + 2][row] = p2; As[k + 3][row] = p3;
            }
        }
#pragma unroll
        for (int p = 0; p < 2; p++) {
            int f = tid + p * 256;
            int ch = f >> 6;
            int o = f & 63;
            int cc = ch0 + ch;
            int col = n0 + o;
            float4 wv = make_float4(0.f, 0.f, 0.f, 0.f);
            if (cc < C_in && col < C_out)
                wv = *reinterpret_cast<const float4*>(&w[((size_t)cc * C_out + col) * 4]);
            int k = ch * 4;
            Bs[k + 0][o] = wv.x; Bs[k + 1][o] = wv.y;
            Bs[k + 2][o] = wv.z; Bs[k + 3][o] = wv.w;
        }
        __syncthreads();

#pragma unroll
        for (int k = 0; k < 32; k++) {
            float a[8], bv[4];
#pragma unroll
            for (int r = 0; r < 8; r++) a[r] = As[k][trow * 8 + r];
#pragma unroll
            for (int c = 0; c < 4; c++) bv[c] = Bs[k][tcol * 4 + c];
#pragma unroll
            for (int r = 0; r < 8; r++)
#pragma unroll
                for (int c = 0; c < 4; c++) acc[r][c] = fmaf(a[r], bv[c], acc[r][c]);
        }
        __syncthreads();
    }

    if (LAST) {
#pragma unroll
        for (int r = 0; r < 8; r++) {
            int m = m0 + trow * 8 + r;
            int bb = m >> 10, n = m & (NPTS - 1);
#pragma unroll
            for (int c = 0; c < 4; c++) {
                int col = n0 + tcol * 4 + c;
                if (col < C_out) out[((size_t)bb * C_out + col) * NPTS + n] = acc[r][c];
            }
        }
    } else {
#pragma unroll
        for (int r = 0; r < 8; r++) {
            size_t m = m0 + trow * 8 + r;
            float4 v = make_float4(acc[r][0], acc[r][1], acc[r][2], acc[r][3]);
            *reinterpret_cast<float4*>(&out[m * C_out + n0 + tcol * 4]) = v;
        }
        float s[4] = {0, 0, 0, 0}, q[4] = {0, 0, 0, 0};
#pragma unroll
        for (int r = 0; r < 8; r++)
#pragma unroll
            for (int c = 0; c < 4; c++) {
                s[c] += acc[r][c];
                q[c] += acc[r][c] * acc[r][c];
            }
#pragma unroll
        for (int c = 0; c < 4; c++) {
            redS[trow][tcol * 4 + c] = s[c];
            redQ[trow][tcol * 4 + c] = q[c];
        }
        __syncthreads();
        if (tid < 64 && (n0 + tid) < C_out) {
            float ts = 0.f, tq = 0.f;
#pragma unroll
            for (int r = 0; r < 16; r++) { ts += redS[r][tid]; tq += redQ[r][tid]; }
            atomicAdd(&ssum[n0 + tid], ts);
            atomicAdd(&ssq[n0 + tid], tq);
        }
    }
}

// ---------------- launch ----------------
static inline int cdiv(int a, int b) { return (a + b - 1) / b; }

extern "C" void kernel_launch(void* const* d_in, const int* in_sizes, int n_in,
                              void* d_out, int out_size) {
    (void)in_sizes; (void)n_in; (void)out_size;
    const float* x   = (const float*)d_in[0];
    const float* w1  = (const float*)d_in[1];
    const float* w2  = (const float*)d_in[2];
    const float* w3  = (const float*)d_in[3];
    const float* w4  = (const float*)d_in[4];
    const float* w5  = (const float*)d_in[5];
    const float* w6  = (const float*)d_in[6];
    const float* w7  = (const float*)d_in[7];
    const float* w8  = (const float*)d_in[8];
    const float* w9  = (const float*)d_in[9];
    const float* w10 = (const float*)d_in[10];
    float* outp = (float*)d_out;

    float *z1, *z2, *z3, *z4, *z6, *z7, *z8, *z9;
    float *sum, *sq, *mean, *rstd, *cst6;
    cudaGetSymbolAddress((void**)&z1, g_z1);
    cudaGetSymbolAddress((void**)&z2, g_z2);
    cudaGetSymbolAddress((void**)&z3, g_z3);
    cudaGetSymbolAddress((void**)&z4, g_z4);
    cudaGetSymbolAddress((void**)&z6, g_z6);
    cudaGetSymbolAddress((void**)&z7, g_z7);
    cudaGetSymbolAddress((void**)&z8, g_z8);
    cudaGetSymbolAddress((void**)&z9, g_z9);
    cudaGetSymbolAddress((void**)&sum, g_sum);
    cudaGetSymbolAddress((void**)&sq, g_sq);
    cudaGetSymbolAddress((void**)&mean, g_mean);
    cudaGetSymbolAddress((void**)&rstd, g_rstd);
    cudaGetSymbolAddress((void**)&cst6, g_const6);

    cudaFuncSetAttribute(kan_mma<false, false>, cudaFuncAttributeMaxDynamicSharedMemorySize, SMEM_MMA);
    cudaFuncSetAttribute(kan_mma<true, false>,  cudaFuncAttributeMaxDynamicSharedMemorySize, SMEM_MMA);
    cudaFuncSetAttribute(kan_mma<false, true>,  cudaFuncAttributeMaxDynamicSharedMemorySize, SMEM_MMA);

    zero_kernel<<<cdiv(BATCH * 1024, 256), 256>>>();

    // L1: x(2) -> z1(64)   [scalar FIRST]
    kan_gemm<true, false><<<dim3(1, 256), 256>>>(
        x, w1, nullptr, nullptr, z1, sum + 0, sq + 0, 2, 64);
    finalize_kernel<<<1, 64>>>(sum + 0, sq + 0, mean + 0, rstd + 0, 64);

    // L2: z1(64) -> z2(64)   [scalar]
    kan_gemm<false, false><<<dim3(1, 256), 256>>>(
        z1, w2, mean + 0, rstd + 0, z2, sum + 64, sq + 64, 64, 64);
    finalize_kernel<<<1, 64>>>(sum + 64, sq + 64, mean + 64, rstd + 64, 64);

    // L3: z2(64) -> z3(64)   [scalar]
    kan_gemm<false, false><<<dim3(1, 256), 256>>>(
        z2, w3, mean + 64, rstd + 64, z3, sum + 128, sq + 128, 64, 64);
    finalize_kernel<<<1, 64>>>(sum + 128, sq + 128, mean + 128, rstd + 128, 64);

    // L4: z3(64) -> z4(128)   [HMMA]
    kan_mma<false, false><<<dim3(2, 256), 256, SMEM_MMA>>>(
        z3, w4, mean + 128, rstd + 128, z4, sum + 192, sq + 192, nullptr, 64, 128);
    finalize_kernel<<<2, 64>>>(sum + 192, sq + 192, mean + 192, rstd + 192, 128);

    // L5: z4(128) -> (maxpool + stats only, z5 never stored)   [HMMA, MAXPOOL]
    kan_mma<true, false><<<dim3(16, 256), 256, SMEM_MMA>>>(
        z4, w5, mean + 192, rstd + 192, nullptr, sum + 320, sq + 320, nullptr, 128, 1024);
    finalize_kernel<<<16, 64>>>(sum + 320, sq + 320, mean + 320, rstd + 320, 1024);

    // gf constant contribution to layer 6
    const6_kernel<<<dim3(8, 8), 64>>>(w6);

    // L6: local z2(64) -> z6(512), + const6   [HMMA, HASCONST]
    kan_mma<false, true><<<dim3(8, 256), 256, SMEM_MMA>>>(
        z2, w6, mean + 64, rstd + 64, z6, sum + 1344, sq + 1344, cst6, 64, 512);
    finalize_kernel<<<8, 64>>>(sum + 1344, sq + 1344, mean + 1344, rstd + 1344, 512);

    // L7: z6(512) -> z7(256)   [HMMA]
    kan_mma<false, false><<<dim3(4, 256), 256, SMEM_MMA>>>(
        z6, w7, mean + 1344, rstd + 1344, z7, sum + 1856, sq + 1856, nullptr, 512, 256);
    finalize_kernel<<<4, 64>>>(sum + 1856, sq + 1856, mean + 1856, rstd + 1856, 256);

    // L8: z7(256) -> z8(128)   [HMMA]
    kan_mma<false, false><<<dim3(2, 256), 256, SMEM_MMA>>>(
        z7, w8, mean + 1856, rstd + 1856, z8, sum + 2112, sq + 2112, nullptr, 256, 128);
    finalize_kernel<<<2, 64>>>(sum + 2112, sq + 2112, mean + 2112, rstd + 2112, 128);

    // L9: z8(128) -> z9(128)   [HMMA]
    kan_mma<false, false><<<dim3(2, 256), 256, SMEM_MMA>>>(
        z8, w9, mean + 2112, rstd + 2112, z9, sum + 2240, sq + 2240, nullptr, 128, 128);
    finalize_kernel<<<2, 64>>>(sum + 2240, sq + 2240, mean + 2240, rstd + 2240, 128);

    // L10: z9(128) -> out (B, 3, N), no BN   [scalar LAST]
    kan_gemm<false, true><<<dim3(1, 256), 256>>>(
        z9, w10, mean + 2240, rstd + 2240, outp, nullptr, nullptr, 128, 3);
}

// round 13
// speedup vs baseline: 1.2945x; 1.2930x over previous
#include <cuda_runtime.h>
#include <cstddef>
#include <cstdint>

#define NPTS 1024
#define BATCH 32
#define MTOT 32768
#define EPS_BN 1e-5f

// ---------------- static scratch (no allocations allowed) ----------------
__device__ float g_z1[(size_t)MTOT * 64];
__device__ float g_z2[(size_t)MTOT * 64];
__device__ float g_z3[(size_t)MTOT * 64];
__device__ float g_z4[(size_t)MTOT * 128];
// z5 is never materialized: max-pool + stats are fused into the L5 GEMM epilogue
__device__ float g_z6[(size_t)MTOT * 512];
__device__ float g_z7[(size_t)MTOT * 256];
__device__ float g_z8[(size_t)MTOT * 128];
__device__ float g_z9[(size_t)MTOT * 128];

// preconverted split-bf16 weights, stored as the exact SMEM B-tile byte image:
// per (layer, nblk, kt) tile: 16KB hi + 16KB lo = 2048 uint4
// L4:4 L5:64 L6:16 L7:64 L8:16 L9:8 tiles -> 172 tiles
__device__ uint4 g_wt[172 * 2048];

// per-channel stats, packed by layer offset:
// L1:0(64) L2:64 L3:128 L4:192(128) L5:320(1024) L6:1344(512) L7:1856(256) L8:2112(128) L9:2240(128) -> 2368
__device__ float g_sum[2368];
__device__ float g_sq[2368];
__device__ float g_mean[2368];
__device__ float g_rstd[2368];

__device__ unsigned g_max5[BATCH * 1024];   // order-monotone uint-mapped float max
__device__ float g_const6[BATCH * 512];     // per-batch gf contribution to layer 6

// ---------------- helpers ----------------
__device__ __forceinline__ float fast_tanh(float x) {
    // tanh(x) = 1 - 2/(exp(2x)+1); ex2.approx + rcp.approx, rel err ~1e-6
    float e, r;
    asm("ex2.approx.f32 %0, %1;" : "=f"(e) : "f"(x * 2.8853900817779268f)); // 2*log2(e)
    asm("rcp.approx.f32 %0, %1;" : "=f"(r) : "f"(e + 1.0f));
    return 1.0f - 2.0f * r;
}

// Jacobi polys, degree 3, a=b=1 (exact constants from the reference recurrence)
__device__ __forceinline__ void jacobi4(float t, float& p0, float& p1, float& p2, float& p3) {
    p0 = 1.0f;
    p1 = 2.0f * t;
    p2 = 1.875f * t * p1 - 0.75f;
    p3 = 1.8666666666666667f * t * p2 - 0.8f * p1;
}

__device__ __forceinline__ unsigned fmap(float f) {
    unsigned u = __float_as_uint(f);
    return (u & 0x80000000u) ? ~u : (u | 0x80000000u);
}
__device__ __forceinline__ float funmap(unsigned u) {
    return (u & 0x80000000u) ? __uint_as_float(u & 0x7fffffffu) : __uint_as_float(~u);
}

static __device__ __forceinline__ uint32_t smem_u32(const void* p) {
    uint32_t a;
    asm("{ .reg .u64 t; cvta.to.shared.u64 t, %1; cvt.u32.u64 %0, t; }" : "=r"(a) : "l"(p));
    return a;
}

__device__ __forceinline__ unsigned pack_bf16(float lo, float hi) {
    // result low 16 bits = bf16(lo), high = bf16(hi)
    unsigned r;
    asm("cvt.rn.bf16x2.f32 %0, %1, %2;" : "=r"(r) : "f"(hi), "f"(lo));
    return r;
}
// split 8 consecutive fp32 values into hi/lo bf16x2 quads (memory order preserved)
__device__ __forceinline__ void split8(const float* v, uint4& hi, uint4& lo) {
    unsigned h[4], l[4];
#pragma unroll
    for (int g = 0; g < 4; g++) {
        float a0 = v[2 * g], a1 = v[2 * g + 1];
        unsigned p = pack_bf16(a0, a1);
        float h0 = __uint_as_float(p << 16);
        float h1 = __uint_as_float(p & 0xffff0000u);
        h[g] = p;
        l[g] = pack_bf16(a0 - h0, a1 - h1);
    }
    hi = make_uint4(h[0], h[1], h[2], h[3]);
    lo = make_uint4(l[0], l[1], l[2], l[3]);
}

__device__ __forceinline__ void ldsm4(uint32_t addr, uint32_t* r) {
    asm volatile("ldmatrix.sync.aligned.m8n8.x4.shared.b16 {%0,%1,%2,%3}, [%4];"
                 : "=r"(r[0]), "=r"(r[1]), "=r"(r[2]), "=r"(r[3]) : "r"(addr));
}

__device__ __forceinline__ void mma16816(float* c, const uint32_t* a, uint32_t b0, uint32_t b1) {
    asm volatile(
        "mma.sync.aligned.m16n8k16.row.col.f32.bf16.bf16.f32 "
        "{%0,%1,%2,%3}, {%4,%5,%6,%7}, {%8,%9}, {%0,%1,%2,%3};"
        : "+f"(c[0]), "+f"(c[1]), "+f"(c[2]), "+f"(c[3])
        : "r"(a[0]), "r"(a[1]), "r"(a[2]), "r"(a[3]), "r"(b0), "r"(b1));
}

__device__ __forceinline__ void cpasync16(uint32_t dst, const void* src) {
    asm volatile("cp.async.cg.shared.global [%0], [%1], 16;" :: "r"(dst), "l"(src) : "memory");
}
#define CP_COMMIT() asm volatile("cp.async.commit_group;" ::: "memory")
#define CP_WAIT_ALL() asm volatile("cp.async.wait_group 0;" ::: "memory")

// SMEM layout of the tensor kernel (byte offsets from a 1024-aligned base)
#define OFF_RAWA 0                 // 2 x 8KB raw fp32 A tiles (double buffer)
#define OFF_B    16384             // 2 x 32KB preconverted B tiles (hi16+lo16 each)
#define OFF_AS   81920             // converted A: hi 16KB + lo 16KB (single buffer)
#define OFF_CST  114688
#define SMEM_MMA (OFF_CST + 512 + 1024)   // 116224

// ---------------- tiny kernels ----------------
__global__ void zero_kernel() {
    int i = blockIdx.x * 256 + threadIdx.x;
    if (i < 2368) { g_sum[i] = 0.f; g_sq[i] = 0.f; }
    if (i < BATCH * 1024) g_max5[i] = 0u;  // 0 < fmap(any finite float)
}

__global__ void finalize_kernel(const float* __restrict__ s, const float* __restrict__ q,
                                float* __restrict__ mean, float* __restrict__ rstd, int C) {
    int i = blockIdx.x * 64 + threadIdx.x;
    if (i < C) {
        float m = s[i] * (1.0f / 32768.0f);
        float v = q[i] * (1.0f / 32768.0f) - m * m;
        mean[i] = m;
        rstd[i] = rsqrtf(v + EPS_BN);
    }
}

// Preconvert one layer's weights into swizzled split-bf16 B-tile images.
// grid = numKT * numNB blocks; block (kt, nblk) writes tile [nblk*numKT + kt].
__global__ void prep_w_kernel(const float* __restrict__ w, int C_in, int C_out, int base_u4) {
    const int numKT = C_in >> 4;
    const int kt = blockIdx.x % numKT;
    const int nblk = blockIdx.x / numKT;
    const int ch0 = kt * 16;
    const int n0 = nblk * 128;
    uint4* dst = g_wt + base_u4 + (size_t)blockIdx.x * 2048;   // blockIdx.x = nblk*numKT+kt
    const size_t chstride = (size_t)C_out * 4;
#pragma unroll
    for (int i = 0; i < 4; i++) {
        const int task = threadIdx.x + i * 256;   // 1024 tasks: 128 rows x 8 pairs
        const int row = task >> 3;
        const int p = task & 7;
        const size_t idx0 = ((size_t)(ch0 + 2 * p) * C_out + (n0 + row)) * 4;
        float4 w0 = *reinterpret_cast<const float4*>(&w[idx0]);
        float4 w1 = *reinterpret_cast<const float4*>(&w[idx0 + chstride]);
        const float v8[8] = {w0.x, w0.y, w0.z, w0.w, w1.x, w1.y, w1.z, w1.w};
        uint4 hi, lo;
        split8(v8, hi, lo);
        const uint32_t byte = (((uint32_t)row >> 3) << 10) + (((uint32_t)row & 7) << 7)
                              + (((uint32_t)p * 16) ^ (((uint32_t)row & 7) << 4));
        dst[byte >> 4] = hi;
        dst[1024 + (byte >> 4)] = lo;
    }
}

// const6[b][o] = sum_{i in [0,1024)} phi(tanh(BN5(max5[b][i]))) . w6[64+i][o][:]
__global__ void const6_kernel(const float* __restrict__ w6) {
    __shared__ float sb[4][256][4];   // 16KB staged basis
    const int b0 = blockIdx.y * 4;
    const int o = blockIdx.x * 64 + threadIdx.x;
    const float* mean5 = &g_mean[320];
    const float* rstd5 = &g_rstd[320];
    float acc[4] = {0.f, 0.f, 0.f, 0.f};
    for (int i0 = 0; i0 < 1024; i0 += 256) {
        for (int e = threadIdx.x; e < 1024; e += 64) {
            int bj = e >> 8, i = e & 255;
            float f = funmap(g_max5[(b0 + bj) * 1024 + i0 + i]);
            float t = fast_tanh((f - mean5[i0 + i]) * rstd5[i0 + i]);
            float p0, p1, p2, p3;
            jacobi4(t, p0, p1, p2, p3);
            sb[bj][i][0] = p0; sb[bj][i][1] = p1;
            sb[bj][i][2] = p2; sb[bj][i][3] = p3;
        }
        __syncthreads();
#pragma unroll 4
        for (int i = 0; i < 256; i++) {
            float4 wv = *reinterpret_cast<const float4*>(&w6[((size_t)(64 + i0 + i) * 512 + o) * 4]);
#pragma unroll
            for (int bj = 0; bj < 4; bj++)
                acc[bj] += sb[bj][i][0] * wv.x + sb[bj][i][1] * wv.y +
                           sb[bj][i][2] * wv.z + sb[bj][i][3] * wv.w;
        }
        __syncthreads();
    }
#pragma unroll
    for (int bj = 0; bj < 4; bj++) g_const6[(b0 + bj) * 512 + o] = acc[bj];
}

// ======================= split-bf16 HMMA KAN GEMM (heavy layers) =======================
// BM=128 x BN=128, BK=64 (16 channels x 4 bases), 256 threads (8 warps, 2Mx4N grid).
// D = Ah*Bh^T + Ah*Bl^T + Al*Bh^T in fp32 accumulators via mma.sync.m16n8k16.bf16.
// Per k-tile: cp.async-staged raw A (fp32) + preconverted B (bf16 tile image),
// double-buffered; only the A basis conversion is serial work.
// Requires C_in % 16 == 0, C_out % 128 == 0. BN applied to input (mean/rstd).
template <bool MAXPOOL, bool HASCONST>
__global__ __launch_bounds__(256)
void kan_mma(const float* __restrict__ in, const uint4* __restrict__ wt,
             const float* __restrict__ mean, const float* __restrict__ rstd,
             float* __restrict__ out, float* __restrict__ ssum, float* __restrict__ ssq,
             const float* __restrict__ cst, int C_in, int C_out)
{
    extern __shared__ char dsm[];
    const uint32_t raw32 = smem_u32(dsm);
    const uint32_t ab32 = (raw32 + 1023u) & ~1023u;
    char* ab = dsm + (ab32 - raw32);

    const int tid = threadIdx.x;
    const int lane = tid & 31;
    const int wid = tid >> 5;
    const int m0 = blockIdx.y * 128;
    const int n0 = blockIdx.x * 128;
    const int b = m0 >> 10;             // 128-row tiles never cross batch

    float* cst_s = reinterpret_cast<float*>(ab + OFF_CST);
    if (HASCONST && tid < 128) cst_s[tid] = cst[(size_t)b * C_out + n0 + tid];

    float acc[4][4][4];
#pragma unroll
    for (int mi = 0; mi < 4; mi++)
#pragma unroll
        for (int ni = 0; ni < 4; ni++)
#pragma unroll
            for (int r = 0; r < 4; r++) acc[mi][ni][r] = 0.f;

    const int numKT = C_in >> 4;
    const uint4* wtile0 = wt + (size_t)blockIdx.x * numKT * 2048;

    // staging thread mapping
    const int arow = tid >> 1;          // cvt: 2 threads/row, 8 channels each
    const int achq = (tid & 1) * 8;

    // warp MMA mapping (R9): 2 warps in M (64 rows), 4 warps in N (32 cols)
    const int mw = (wid >> 2) * 64;
    const int nw = (wid & 3) * 32;
    const int rof = lane & 15;
    const int klo = (lane >> 4) * 16;
    const int rbase = ((rof >> 3) << 10) + ((rof & 7) << 7);
    const int rxor = (rof & 7) << 4;

    const uint32_t AH = ab32 + OFF_AS, AL = ab32 + OFF_AS + 16384;

    auto STAGE = [&](int kt) {   // cp.async raw A (8KB) + B tile (32KB) into buffer kt&1
        const uint32_t rbuf = ab32 + OFF_RAWA + (uint32_t)(kt & 1) * 8192;
        const int ch0 = kt * 16;
#pragma unroll
        for (int h = 0; h < 2; h++) {
            const int s = tid + h * 256;       // 512 segments of 16B
            const int row = s >> 2, part = s & 3;
            cpasync16(rbuf + (uint32_t)s * 16,
                      &in[(size_t)(m0 + row) * C_in + ch0 + part * 4]);
        }
        const uint32_t bbuf = ab32 + OFF_B + (uint32_t)(kt & 1) * 32768;
        const uint4* src = wtile0 + (size_t)kt * 2048 + tid * 8;
#pragma unroll
        for (int h = 0; h < 8; h++)
            cpasync16(bbuf + (uint32_t)(tid * 8 + h) * 16, src + h);
        CP_COMMIT();
    };

    // prologue
    STAGE(0);
    CP_WAIT_ALL();
    __syncthreads();

    for (int kt = 0; kt < numKT; kt++) {
        // issue next tile's staging now; it lands during cvt + MMA below
        if (kt + 1 < numKT) STAGE(kt + 1);

        // ---- A convert: raw fp32 (smem) -> basis -> bf16 hi/lo, SW128 ----
        {
            const float* rawa = reinterpret_cast<const float*>(
                ab + OFF_RAWA + (uint32_t)(kt & 1) * 8192);
            const int ch0 = kt * 16;
            float4 v4a = *reinterpret_cast<const float4*>(&rawa[arow * 16 + achq]);
            float4 v4b = *reinterpret_cast<const float4*>(&rawa[arow * 16 + achq + 4]);
            const float vv[8] = {v4a.x, v4a.y, v4a.z, v4a.w, v4b.x, v4b.y, v4b.z, v4b.w};
            const uint32_t offr = ((uint32_t)(arow >> 3) << 10) + ((uint32_t)(arow & 7) << 7);
            const uint32_t rx = (uint32_t)(arow & 7) << 4;
#pragma unroll
            for (int p = 0; p < 4; p++) {       // channel pairs, small live set
                const int c0 = achq + 2 * p;
                float t0 = fast_tanh((vv[2 * p] - mean[ch0 + c0]) * rstd[ch0 + c0]);
                float t1 = fast_tanh((vv[2 * p + 1] - mean[ch0 + c0 + 1]) * rstd[ch0 + c0 + 1]);
                float v8[8];
                jacobi4(t0, v8[0], v8[1], v8[2], v8[3]);
                jacobi4(t1, v8[4], v8[5], v8[6], v8[7]);
                uint4 hi, lo;
                split8(v8, hi, lo);
                const uint32_t sw = offr + ((((uint32_t)c0 >> 1) * 16) ^ rx);
                *reinterpret_cast<uint4*>(ab + OFF_AS + sw) = hi;
                *reinterpret_cast<uint4*>(ab + OFF_AS + 16384 + sw) = lo;
            }
        }
        __syncthreads();   // As visible to all warps

        // ---- HMMA: 4 k16 chunks x (AhBh + AhBl + AlBh) ----
        const uint32_t bb = ab32 + OFF_B + (uint32_t)(kt & 1) * 32768;
        const uint32_t BH = bb, BL = bb + 16384;
#pragma unroll
        for (int ks = 0; ks < 4; ks++) {
            const uint32_t kb = ks * 32;
            uint32_t ah[4][4];
#pragma unroll
            for (int mi = 0; mi < 4; mi++) {
                const uint32_t off = ((uint32_t)((mw + mi * 16) >> 3) << 10) + rbase
                                     + ((kb + klo) ^ rxor);
                ldsm4(AH + off, ah[mi]);
            }
            uint32_t bh[2][4], bl[2][4];
#pragma unroll
            for (int nj = 0; nj < 2; nj++) {
                const uint32_t off = ((uint32_t)((nw + nj * 16) >> 3) << 10) + rbase
                                     + ((kb + klo) ^ rxor);
                ldsm4(BH + off, bh[nj]);
                ldsm4(BL + off, bl[nj]);
            }
#pragma unroll
            for (int mi = 0; mi < 4; mi++)
#pragma unroll
                for (int ni = 0; ni < 4; ni++) {
                    const int nj = ni >> 1, s = ni & 1;
                    mma16816(acc[mi][ni], ah[mi], bh[nj][s], bh[nj][s + 2]);
                    mma16816(acc[mi][ni], ah[mi], bl[nj][s], bl[nj][s + 2]);
                }
            uint32_t al[4][4];
#pragma unroll
            for (int mi = 0; mi < 4; mi++) {
                const uint32_t off = ((uint32_t)((mw + mi * 16) >> 3) << 10) + rbase
                                     + ((kb + klo) ^ rxor);
                ldsm4(AL + off, al[mi]);
            }
#pragma unroll
            for (int mi = 0; mi < 4; mi++)
#pragma unroll
                for (int ni = 0; ni < 4; ni++) {
                    const int nj = ni >> 1, s = ni & 1;
                    mma16816(acc[mi][ni], al[mi], bh[nj][s], bh[nj][s + 2]);
                }
        }

        // wait for the staged next tile + barrier before reusing buffers
        if (kt + 1 < numKT) CP_WAIT_ALL();
        __syncthreads();
    }

    // ---- epilogue: frags -> smem [128][130] fp32, then coalesced store + stats ----
    float* scr = reinterpret_cast<float*>(ab);
#pragma unroll
    for (int mi = 0; mi < 4; mi++)
#pragma unroll
        for (int ni = 0; ni < 4; ni++)
#pragma unroll
            for (int r = 0; r < 4; r++) {
                const int ml = mw + mi * 16 + (lane >> 2) + (r >> 1) * 8;
                const int nl = nw + ni * 8 + (lane & 3) * 2 + (r & 1);
                float v = acc[mi][ni][r];
                if (HASCONST) v += cst_s[nl];
                scr[ml * 130 + nl] = v;
            }
    __syncthreads();

    if (!MAXPOOL) {
#pragma unroll 4
        for (int i = 0; i < 16; i++) {
            const int r = wid * 16 + i;
            const float* row = &scr[r * 130 + lane * 4];
            *reinterpret_cast<float4*>(&out[(size_t)(m0 + r) * C_out + n0 + lane * 4]) =
                make_float4(row[0], row[1], row[2], row[3]);
        }
    }
    if (tid < 128) {
        float s = 0.f, q = 0.f, mx = -3.4e38f;
        for (int r = 0; r < 128; r++) {
            float v = scr[r * 130 + tid];
            s += v; q += v * v;
            if (MAXPOOL) mx = fmaxf(mx, v);
        }
        atomicAdd(&ssum[n0 + tid], s);
        atomicAdd(&ssq[n0 + tid], q);
        if (MAXPOOL) atomicMax(&g_max5[b * 1024 + n0 + tid], fmap(mx));
    }
}

// ======================= scalar GEMM (edge layers: L1, L2, L3, L10) =======================
template <bool FIRST, bool LAST>
__global__ __launch_bounds__(256) void kan_gemm(
    const float* __restrict__ in, const float* __restrict__ w,
    const float* __restrict__ mean, const float* __restrict__ rstd,
    float* __restrict__ out, float* __restrict__ ssum, float* __restrict__ ssq,
    int C_in, int C_out)
{
    __shared__ float As[32][128];
    __shared__ float Bs[32][64];
    __shared__ float redS[16][64];
    __shared__ float redQ[16][64];

    const int tid = threadIdx.x;
    const int tcol = tid & 15, trow = tid >> 4;
    const int m0 = blockIdx.y * 128;
    const int n0 = blockIdx.x * 64;

    float acc[8][4];
#pragma unroll
    for (int r = 0; r < 8; r++)
#pragma unroll
        for (int c = 0; c < 4; c++) acc[r][c] = 0.f;

    const int numKT = (C_in + 7) >> 3;
    for (int kt = 0; kt < numKT; kt++) {
        const int ch0 = kt * 8;
        if (FIRST) {
            const int ch = tid & 7;
            const int rb = tid >> 3;
#pragma unroll
            for (int p = 0; p < 4; p++) {
                int row = rb + p * 32;
                float p0 = 0.f, p1 = 0.f, p2 = 0.f, p3 = 0.f;
                if (ch0 + ch < C_in) {
                    int m = m0 + row;
                    float v = in[(m >> 10) * (2 * NPTS) + (ch0 + ch) * NPTS + (m & (NPTS - 1))];
                    float t = fast_tanh(v);
                    jacobi4(t, p0, p1, p2, p3);
                }
                int k = ch * 4;
                As[k + 0][row] = p0; As[k + 1][row] = p1;
                As[k + 2][row] = p2; As[k + 3][row] = p3;
            }
        } else {
            const int row = tid >> 1;
            const int chq = (tid & 1) * 4;
            const float4 v4 =
                *reinterpret_cast<const float4*>(&in[(size_t)(m0 + row) * C_in + ch0 + chq]);
            const float vv[4] = {v4.x, v4.y, v4.z, v4.w};
#pragma unroll
            for (int j = 0; j < 4; j++) {
                int cc = ch0 + chq + j;
                float t = fast_tanh((vv[j] - mean[cc]) * rstd[cc]);
                float p0, p1, p2, p3;
                jacobi4(t, p0, p1, p2, p3);
                int k = (chq + j) * 4;
                As[k + 0][row] = p0; As[k + 1][row] = p1;
                As[k + 2][row] = p2; As[k + 3][row] = p3;
            }
        }
#pragma unroll
        for (int p = 0; p < 2; p++) {
            int f = tid + p * 256;
            int ch = f >> 6;
            int o = f & 63;
            int cc = ch0 + ch;
            int col = n0 + o;
            float4 wv = make_float4(0.f, 0.f, 0.f, 0.f);
            if (cc < C_in && col < C_out)
                wv = *reinterpret_cast<const float4*>(&w[((size_t)cc * C_out + col) * 4]);
            int k = ch * 4;
            Bs[k + 0][o] = wv.x; Bs[k + 1][o] = wv.y;
            Bs[k + 2][o] = wv.z; Bs[k + 3][o] = wv.w;
        }
        __syncthreads();

#pragma unroll
        for (int k = 0; k < 32; k++) {
            float a[8], bv[4];
#pragma unroll
            for (int r = 0; r < 8; r++) a[r] = As[k][trow * 8 + r];
#pragma unroll
            for (int c = 0; c < 4; c++) bv[c] = Bs[k][tcol * 4 + c];
#pragma unroll
            for (int r = 0; r < 8; r++)
#pragma unroll
                for (int c = 0; c < 4; c++) acc[r][c] = fmaf(a[r], bv[c], acc[r][c]);
        }
        __syncthreads();
    }

    if (LAST) {
#pragma unroll
        for (int r = 0; r < 8; r++) {
            int m = m0 + trow * 8 + r;
            int bb = m >> 10, n = m & (NPTS - 1);
#pragma unroll
            for (int c = 0; c < 4; c++) {
                int col = n0 + tcol * 4 + c;
                if (col < C_out) out[((size_t)bb * C_out + col) * NPTS + n] = acc[r][c];
            }
        }
    } else {
#pragma unroll
        for (int r = 0; r < 8; r++) {
            size_t m = m0 + trow * 8 + r;
            float4 v = make_float4(acc[r][0], acc[r][1], acc[r][2], acc[r][3]);
            *reinterpret_cast<float4*>(&out[m * C_out + n0 + tcol * 4]) = v;
        }
        float s[4] = {0, 0, 0, 0}, q[4] = {0, 0, 0, 0};
#pragma unroll
        for (int r = 0; r < 8; r++)
#pragma unroll
            for (int c = 0; c < 4; c++) {
                s[c] += acc[r][c];
                q[c] += acc[r][c] * acc[r][c];
            }
#pragma unroll
        for (int c = 0; c < 4; c++) {
            redS[trow][tcol * 4 + c] = s[c];
            redQ[trow][tcol * 4 + c] = q[c];
        }
        __syncthreads();
        if (tid < 64 && (n0 + tid) < C_out) {
            float ts = 0.f, tq = 0.f;
#pragma unroll
            for (int r = 0; r < 16; r++) { ts += redS[r][tid]; tq += redQ[r][tid]; }
            atomicAdd(&ssum[n0 + tid], ts);
            atomicAdd(&ssq[n0 + tid], tq);
        }
    }
}

// ---------------- launch ----------------
static inline int cdiv(int a, int b) { return (a + b - 1) / b; }

extern "C" void kernel_launch(void* const* d_in, const int* in_sizes, int n_in,
                              void* d_out, int out_size) {
    (void)in_sizes; (void)n_in; (void)out_size;
    const float* x   = (const float*)d_in[0];
    const float* w1  = (const float*)d_in[1];
    const float* w2  = (const float*)d_in[2];
    const float* w3  = (const float*)d_in[3];
    const float* w4  = (const float*)d_in[4];
    const float* w5  = (const float*)d_in[5];
    const float* w6  = (const float*)d_in[6];
    const float* w7  = (const float*)d_in[7];
    const float* w8  = (const float*)d_in[8];
    const float* w9  = (const float*)d_in[9];
    const float* w10 = (const float*)d_in[10];
    float* outp = (float*)d_out;

    float *z1, *z2, *z3, *z4, *z6, *z7, *z8, *z9;
    float *sum, *sq, *mean, *rstd, *cst6;
    uint4* wt;
    cudaGetSymbolAddress((void**)&z1, g_z1);
    cudaGetSymbolAddress((void**)&z2, g_z2);
    cudaGetSymbolAddress((void**)&z3, g_z3);
    cudaGetSymbolAddress((void**)&z4, g_z4);
    cudaGetSymbolAddress((void**)&z6, g_z6);
    cudaGetSymbolAddress((void**)&z7, g_z7);
    cudaGetSymbolAddress((void**)&z8, g_z8);
    cudaGetSymbolAddress((void**)&z9, g_z9);
    cudaGetSymbolAddress((void**)&sum, g_sum);
    cudaGetSymbolAddress((void**)&sq, g_sq);
    cudaGetSymbolAddress((void**)&mean, g_mean);
    cudaGetSymbolAddress((void**)&rstd, g_rstd);
    cudaGetSymbolAddress((void**)&cst6, g_const6);
    cudaGetSymbolAddress((void**)&wt, g_wt);

    cudaFuncSetAttribute(kan_mma<false, false>, cudaFuncAttributeMaxDynamicSharedMemorySize, SMEM_MMA);
    cudaFuncSetAttribute(kan_mma<true, false>,  cudaFuncAttributeMaxDynamicSharedMemorySize, SMEM_MMA);
    cudaFuncSetAttribute(kan_mma<false, true>,  cudaFuncAttributeMaxDynamicSharedMemorySize, SMEM_MMA);

    zero_kernel<<<cdiv(BATCH * 1024, 256), 256>>>();

    // weight preconversion (stats-independent; tile bases in uint4 units)
    prep_w_kernel<<<4,  256>>>(w4, 64,  128,  0);       // L4: 4 tiles
    prep_w_kernel<<<64, 256>>>(w5, 128, 1024, 8192);    // L5: 64 tiles
    prep_w_kernel<<<16, 256>>>(w6, 64,  512,  139264);  // L6 local: 16 tiles
    prep_w_kernel<<<64, 256>>>(w7, 512, 256,  172032);  // L7: 64 tiles
    prep_w_kernel<<<16, 256>>>(w8, 256, 128,  303104);  // L8: 16 tiles
    prep_w_kernel<<<8,  256>>>(w9, 128, 128,  335872);  // L9: 8 tiles

    // L1: x(2) -> z1(64)   [scalar FIRST]
    kan_gemm<true, false><<<dim3(1, 256), 256>>>(
        x, w1, nullptr, nullptr, z1, sum + 0, sq + 0, 2, 64);
    finalize_kernel<<<1, 64>>>(sum + 0, sq + 0, mean + 0, rstd + 0, 64);

    // L2: z1(64) -> z2(64)   [scalar]
    kan_gemm<false, false><<<dim3(1, 256), 256>>>(
        z1, w2, mean + 0, rstd + 0, z2, sum + 64, sq + 64, 64, 64);
    finalize_kernel<<<1, 64>>>(sum + 64, sq + 64, mean + 64, rstd + 64, 64);

    // L3: z2(64) -> z3(64)   [scalar]
    kan_gemm<false, false><<<dim3(1, 256), 256>>>(
        z2, w3, mean + 64, rstd + 64, z3, sum + 128, sq + 128, 64, 64);
    finalize_kernel<<<1, 64>>>(sum + 128, sq + 128, mean + 128, rstd + 128, 64);

    // L4: z3(64) -> z4(128)   [HMMA]
    kan_mma<false, false><<<dim3(1, 256), 256, SMEM_MMA>>>(
        z3, wt + 0, mean + 128, rstd + 128, z4, sum + 192, sq + 192, nullptr, 64, 128);
    finalize_kernel<<<2, 64>>>(sum + 192, sq + 192, mean + 192, rstd + 192, 128);

    // L5: z4(128) -> (maxpool + stats only, z5 never stored)   [HMMA, MAXPOOL]
    kan_mma<true, false><<<dim3(8, 256), 256, SMEM_MMA>>>(
        z4, wt + 8192, mean + 192, rstd + 192, nullptr, sum + 320, sq + 320, nullptr, 128, 1024);
    finalize_kernel<<<16, 64>>>(sum + 320, sq + 320, mean + 320, rstd + 320, 1024);

    // gf constant contribution to layer 6
    const6_kernel<<<dim3(8, 8), 64>>>(w6);

    // L6: local z2(64) -> z6(512), + const6   [HMMA, HASCONST]
    kan_mma<false, true><<<dim3(4, 256), 256, SMEM_MMA>>>(
        z2, wt + 139264, mean + 64, rstd + 64, z6, sum + 1344, sq + 1344, cst6, 64, 512);
    finalize_kernel<<<8, 64>>>(sum + 1344, sq + 1344, mean + 1344, rstd + 1344, 512);

    // L7: z6(512) -> z7(256)   [HMMA]
    kan_mma<false, false><<<dim3(2, 256), 256, SMEM_MMA>>>(
        z6, wt + 172032, mean + 1344, rstd + 1344, z7, sum + 1856, sq + 1856, nullptr, 512, 256);
    finalize_kernel<<<4, 64>>>(sum + 1856, sq + 1856, mean + 1856, rstd + 1856, 256);

    // L8: z7(256) -> z8(128)   [HMMA]
    kan_mma<false, false><<<dim3(1, 256), 256, SMEM_MMA>>>(
        z7, wt + 303104, mean + 1856, rstd + 1856, z8, sum + 2112, sq + 2112, nullptr, 256, 128);
    finalize_kernel<<<2, 64>>>(sum + 2112, sq + 2112, mean + 2112, rstd + 2112, 128);

    // L9: z8(128) -> z9(128)   [HMMA]
    kan_mma<false, false><<<dim3(1, 256), 256, SMEM_MMA>>>(
        z8, wt + 335872, mean + 2112, rstd + 2112, z9, sum + 2240, sq + 2240, nullptr, 128, 128);
    finalize_kernel<<<2, 64>>>(sum + 2240, sq + 2240, mean + 2240, rstd + 2240, 128);

    // L10: z9(128) -> out (B, 3, N), no BN   [scalar LAST]
    kan_gemm<false, true><<<dim3(1, 256), 256>>>(
        z9, w10, mean + 2240, rstd + 2240, outp, nullptr, nullptr, 128, 3);
}